// round 9
// baseline (speedup 1.0000x reference)
#include <cuda_runtime.h>
#include <cuda_fp16.h>
#include <cstdint>

// Problem constants (fixed shapes)
#define T_TOK 4096
#define HDIM  1024
#define FDIM  4096
#define EDIM  8
#define BM 128
#define BN 128
#define PADROWS 9216    // 8192 + 8*128 worst-case segment padding

// GEMM1: BK = 32 halves/slab (2 k16 steps), row = 64B data + 16B pad
#define BKH1 32
#define ROWB1 80
#define NS1 (HDIM / BKH1)   // 32
// GEMM2: BK = 64 halves/slab (4 k16 steps), row = 128B data + 16B pad
#define BKH2 64
#define ROWB2 144
#define NS2 (FDIM / BKH2)   // 64

// ---------------- scratch (static device globals; no allocation) ----------
__device__ __align__(16) __half g_x16[(size_t)T_TOK * HDIM];
__device__ __align__(16) __half g_h[(size_t)PADROWS * FDIM];
__device__ __align__(16) float  g_y[(size_t)PADROWS * HDIM];
__device__ int   g_perm_token[PADROWS];
__device__ float g_perm_weight[PADROWS];
__device__ int   g_token_pos[T_TOK * 2];
__device__ int   g_te[T_TOK * 2];
__device__ float g_tw[T_TOK * 2];
__device__ int   g_counts[EDIM];
__device__ int   g_cursor[EDIM];
__device__ int   g_off[EDIM + 1];

// ---------------- helpers ---------------------------------------------------
__device__ __forceinline__ uint32_t h2u(__half2 h) { return *(uint32_t*)&h; }
__device__ __forceinline__ uint32_t f2h2(float a, float b) {
    return h2u(__floats2half2_rn(a, b));
}

__device__ __forceinline__ uint32_t smem_u32(const void* p) {
    uint32_t a;
    asm("{ .reg .u64 t; cvta.to.shared.u64 t, %1; cvt.u32.u64 %0, t; }"
        : "=r"(a) : "l"(p));
    return a;
}

__device__ __forceinline__ void ldsm4(uint32_t& r0, uint32_t& r1,
                                      uint32_t& r2, uint32_t& r3, uint32_t addr) {
    asm volatile("ldmatrix.sync.aligned.m8n8.x4.shared.b16 {%0,%1,%2,%3}, [%4];"
                 : "=r"(r0), "=r"(r1), "=r"(r2), "=r"(r3) : "r"(addr));
}

__device__ __forceinline__ void mma_f16(float c[4], const uint32_t a[4],
                                        uint32_t b0, uint32_t b1) {
    asm volatile(
        "mma.sync.aligned.m16n8k16.row.col.f32.f16.f16.f32 "
        "{%0,%1,%2,%3}, {%4,%5,%6,%7}, {%8,%9}, {%0,%1,%2,%3};\n"
        : "+f"(c[0]), "+f"(c[1]), "+f"(c[2]), "+f"(c[3])
        : "r"(a[0]), "r"(a[1]), "r"(a[2]), "r"(a[3]), "r"(b0), "r"(b1));
}

// ---------------- fp32 -> fp16 conversion (x only; weights convert in-GEMM) ---
__global__ void cvt_kernel(const float* __restrict__ s, __half* __restrict__ d,
                           int n8) {
    int i = blockIdx.x * blockDim.x + threadIdx.x;
    if (i >= n8) return;
    const float4* s4 = (const float4*)s + (size_t)i * 2;
    float4 v0 = s4[0], v1 = s4[1];
    uint4 o;
    o.x = f2h2(v0.x, v0.y);
    o.y = f2h2(v0.z, v0.w);
    o.z = f2h2(v1.x, v1.y);
    o.w = f2h2(v1.z, v1.w);
    ((uint4*)d)[i] = o;
}

// ---------------- init ------------------------------------------------------
__global__ void init_kernel() {
    int i = blockIdx.x * blockDim.x + threadIdx.x;
    if (i < PADROWS) {
        g_perm_token[i] = -1;
        g_perm_weight[i] = 0.f;
    }
    if (i < EDIM) g_counts[i] = 0;
}

// ---------------- router: logits + softmax top2 -----------------------------
__global__ void __launch_bounds__(128) router_kernel(
    const float* __restrict__ x, const float* __restrict__ gw,
    float* __restrict__ logits_out) {
    __shared__ float sgw[EDIM * HDIM];
    int tid = threadIdx.x;
    for (int i = tid; i < EDIM * HDIM; i += 128) sgw[i] = gw[i];
    __syncthreads();

    int warp = tid >> 5, lane = tid & 31;
    int t = blockIdx.x * 4 + warp;
    const float* xr = x + (size_t)t * HDIM;

    float acc[EDIM];
#pragma unroll
    for (int e = 0; e < EDIM; e++) acc[e] = 0.f;
    for (int j = lane; j < HDIM; j += 32) {
        float xv = xr[j];
#pragma unroll
        for (int e = 0; e < EDIM; e++) acc[e] = fmaf(xv, sgw[e * HDIM + j], acc[e]);
    }
#pragma unroll
    for (int e = 0; e < EDIM; e++)
#pragma unroll
        for (int o = 16; o > 0; o >>= 1)
            acc[e] += __shfl_xor_sync(0xffffffffu, acc[e], o);

    if (lane == 0) {
#pragma unroll
        for (int e = 0; e < EDIM; e++) logits_out[t * EDIM + e] = acc[e];
        int e0 = 0; float l0 = acc[0];
#pragma unroll
        for (int e = 1; e < EDIM; e++) if (acc[e] > l0) { l0 = acc[e]; e0 = e; }
        int e1 = -1; float l1 = -3.4e38f;
#pragma unroll
        for (int e = 0; e < EDIM; e++)
            if (e != e0 && acc[e] > l1) { l1 = acc[e]; e1 = e; }
        float r = expf(l1 - l0);
        float w0 = 1.f / (1.f + r);
        float w1 = r / (1.f + r);
        g_te[t * 2 + 0] = e0; g_tw[t * 2 + 0] = w0;
        g_te[t * 2 + 1] = e1; g_tw[t * 2 + 1] = w1;
        atomicAdd(&g_counts[e0], 1);
        atomicAdd(&g_counts[e1], 1);
    }
}

// ---------------- scan ------------------------------------------------------
__global__ void scan_kernel() {
    int off = 0;
    for (int e = 0; e < EDIM; e++) {
        g_off[e] = off;
        g_cursor[e] = off;
        off += ((g_counts[e] + BM - 1) / BM) * BM;
    }
    g_off[EDIM] = off;
}

// ---------------- scatter ---------------------------------------------------
__global__ void scatter_kernel() {
    int t = blockIdx.x * blockDim.x + threadIdx.x;
    if (t >= T_TOK) return;
#pragma unroll
    for (int k = 0; k < 2; k++) {
        int e = g_te[t * 2 + k];
        int pos = atomicAdd(&g_cursor[e], 1);
        g_perm_token[pos] = t;
        g_perm_weight[pos] = g_tw[t * 2 + k];
        g_token_pos[t * 2 + k] = pos;
    }
}

// ---------------- GEMM1: h = silu(x@w1^T) * (x@w3^T) * route_w ---------------
// 256 threads / 8 warps; B staged from fp32 with in-register cvt after mma loop.
__global__ void __launch_bounds__(256, 1) gemm1_kernel(
    const float* __restrict__ gup) {
    extern __shared__ char sm1[];
    const uint32_t ABUF = 128 * ROWB1;           // 10240
    const uint32_t GOFF = 128 * ROWB1;           // up section inside B buffer
    const uint32_t BBUF = 2 * 128 * ROWB1;       // 20480
    char* Asm = sm1;
    char* Bsm = sm1 + 2 * ABUF;
    uint32_t asB = smem_u32(Asm);
    uint32_t bsB = smem_u32(Bsm);

    int m0 = blockIdx.x * BM;
    if (m0 >= g_off[EDIM]) return;
    int n0 = blockIdx.y * BN;
    int e = 0;
    while (m0 >= g_off[e + 1]) e++;

    int tid = threadIdx.x;
    int r = tid >> 1;             // staging row 0..127
    int seg = tid & 1;            // 32B (16-half / 16-float) segment

    int tok = g_perm_token[m0 + r];
    const __half* arow = (tok >= 0)
        ? g_x16 + (size_t)tok * HDIM + seg * 16 : nullptr;
    const float* grow = gup + ((size_t)e * 2 * FDIM + (n0 + r)) * HDIM + seg * 16;
    const float* urow = grow + (size_t)FDIM * HDIM;
    uint32_t stoff = (uint32_t)(r * ROWB1 + seg * 32);

    int warp = tid >> 5, lane = tid & 31;
    int gid = lane >> 2, tig = lane & 3;
    int wm = (warp & 1) * 64;
    int wn = (warp >> 1) * 32;

    uint32_t aLrow = (uint32_t)(wm + (lane & 15));
    uint32_t aLcol = (uint32_t)((lane >> 4) * 16);
    uint32_t bLrow = (uint32_t)(wn + (lane & 7) + ((lane >> 4) & 1) * 8);
    uint32_t bLcol = (uint32_t)(((lane >> 3) & 1) * 16);

    float acc[2][4][4][4];
#pragma unroll
    for (int g = 0; g < 2; g++)
#pragma unroll
        for (int mt = 0; mt < 4; mt++)
#pragma unroll
            for (int nt = 0; nt < 4; nt++)
#pragma unroll
                for (int i = 0; i < 4; i++) acc[g][mt][nt][i] = 0.f;

    const uint4 z4 = make_uint4(0, 0, 0, 0);
    uint4 pA[2], hG[2], hU[2];
    float4 gf[4], uf[4];

    // prologue: slab 0 loaded and converted up front
#pragma unroll
    for (int i = 0; i < 2; i++)
        pA[i] = arow ? *(const uint4*)(arow + i * 8) : z4;
#pragma unroll
    for (int j = 0; j < 4; j++) {
        gf[j] = *(const float4*)(grow + j * 4);
        uf[j] = *(const float4*)(urow + j * 4);
    }
#pragma unroll
    for (int j = 0; j < 2; j++) {
        hG[j] = make_uint4(f2h2(gf[2*j].x, gf[2*j].y), f2h2(gf[2*j].z, gf[2*j].w),
                           f2h2(gf[2*j+1].x, gf[2*j+1].y), f2h2(gf[2*j+1].z, gf[2*j+1].w));
        hU[j] = make_uint4(f2h2(uf[2*j].x, uf[2*j].y), f2h2(uf[2*j].z, uf[2*j].w),
                           f2h2(uf[2*j+1].x, uf[2*j+1].y), f2h2(uf[2*j+1].z, uf[2*j+1].w));
    }

    for (int s = 0; s < NS1; s++) {
        int buf = s & 1;
        char* At = Asm + buf * ABUF;
        char* Bt = Bsm + buf * BBUF;
#pragma unroll
        for (int i = 0; i < 2; i++) {
            *(uint4*)(At + stoff + i * 16) = pA[i];
            *(uint4*)(Bt + stoff + i * 16) = hG[i];
            *(uint4*)(Bt + GOFF + stoff + i * 16) = hU[i];
        }
        __syncthreads();     // single barrier per slab (double-buffer safe)

        bool more = (s + 1 < NS1);
        if (more) {
            int k = (s + 1) * BKH1;
#pragma unroll
            for (int i = 0; i < 2; i++)
                pA[i] = arow ? *(const uint4*)(arow + k + i * 8) : z4;
#pragma unroll
            for (int j = 0; j < 4; j++) {
                gf[j] = *(const float4*)(grow + k + j * 4);
                uf[j] = *(const float4*)(urow + k + j * 4);
            }
        }

        uint32_t aTile = asB + buf * ABUF;
        uint32_t bTile = bsB + buf * BBUF;
#pragma unroll
        for (int ks = 0; ks < 2; ks++) {
            uint32_t kbA = ks * 32 + aLcol;
            uint32_t kbB = ks * 32 + bLcol;
            uint32_t a[4][4];
#pragma unroll
            for (int mt = 0; mt < 4; mt++)
                ldsm4(a[mt][0], a[mt][1], a[mt][2], a[mt][3],
                      aTile + (aLrow + mt * 16) * ROWB1 + kbA);
#pragma unroll
            for (int g = 0; g < 2; g++) {
#pragma unroll
                for (int np = 0; np < 2; np++) {
                    uint32_t b0, b1, b2, b3;
                    ldsm4(b0, b1, b2, b3,
                          bTile + g * GOFF + (bLrow + np * 16) * ROWB1 + kbB);
#pragma unroll
                    for (int mt = 0; mt < 4; mt++) {
                        mma_f16(acc[g][mt][np * 2 + 0], a[mt], b0, b1);
                        mma_f16(acc[g][mt][np * 2 + 1], a[mt], b2, b3);
                    }
                }
            }
        }

        if (more) {   // cvt after mma loop: LDG latency stayed covered
#pragma unroll
            for (int j = 0; j < 2; j++) {
                hG[j] = make_uint4(f2h2(gf[2*j].x, gf[2*j].y), f2h2(gf[2*j].z, gf[2*j].w),
                                   f2h2(gf[2*j+1].x, gf[2*j+1].y), f2h2(gf[2*j+1].z, gf[2*j+1].w));
                hU[j] = make_uint4(f2h2(uf[2*j].x, uf[2*j].y), f2h2(uf[2*j].z, uf[2*j].w),
                                   f2h2(uf[2*j+1].x, uf[2*j+1].y), f2h2(uf[2*j+1].z, uf[2*j+1].w));
            }
        }
    }

    // epilogue: silu(gate) * up * routing_weight -> fp16 g_h
#pragma unroll
    for (int mt = 0; mt < 4; mt++) {
        int rbase = m0 + wm + mt * 16 + gid;
        float wA = g_perm_weight[rbase];
        float wB = g_perm_weight[rbase + 8];
#pragma unroll
        for (int nt = 0; nt < 4; nt++) {
            int cbase = n0 + wn + nt * 8 + 2 * tig;
            float h0 = (acc[0][mt][nt][0] / (1.f + expf(-acc[0][mt][nt][0]))) *
                       acc[1][mt][nt][0] * wA;
            float h1 = (acc[0][mt][nt][1] / (1.f + expf(-acc[0][mt][nt][1]))) *
                       acc[1][mt][nt][1] * wA;
            float h2 = (acc[0][mt][nt][2] / (1.f + expf(-acc[0][mt][nt][2]))) *
                       acc[1][mt][nt][2] * wB;
            float h3 = (acc[0][mt][nt][3] / (1.f + expf(-acc[0][mt][nt][3]))) *
                       acc[1][mt][nt][3] * wB;
            *(uint32_t*)&g_h[(size_t)rbase * FDIM + cbase] = f2h2(h0, h1);
            *(uint32_t*)&g_h[(size_t)(rbase + 8) * FDIM + cbase] = f2h2(h2, h3);
        }
    }
}

// ---------------- GEMM2: y = h @ w2^T ----------------------------------------
// A fp16 from g_h; B staged from fp32 dw with in-register cvt. BK=64 halves.
__global__ void __launch_bounds__(256, 1) gemm2_kernel(
    const float* __restrict__ dw) {
    extern __shared__ char sm2[];
    const uint32_t ABUF = 128 * ROWB2;   // 18432
    const uint32_t BBUF = 128 * ROWB2;
    char* Asm = sm2;
    char* Bsm = sm2 + 2 * ABUF;
    uint32_t asB = smem_u32(Asm);
    uint32_t bsB = smem_u32(Bsm);

    int m0 = blockIdx.x * BM;
    if (m0 >= g_off[EDIM]) return;
    int n0 = blockIdx.y * BN;   // over HDIM
    int e = 0;
    while (m0 >= g_off[e + 1]) e++;

    int tid = threadIdx.x;
    int r = tid >> 1;
    int seg = tid & 1;           // 64B (32-half / 32-float) segment

    const __half* arow = g_h + (size_t)(m0 + r) * FDIM + seg * 32;
    const float* brow = dw + ((size_t)e * HDIM + (n0 + r)) * FDIM + seg * 32;
    uint32_t stoff = (uint32_t)(r * ROWB2 + seg * 64);

    int warp = tid >> 5, lane = tid & 31;
    int gid = lane >> 2, tig = lane & 3;
    int wm = (warp & 1) * 64;
    int wn = (warp >> 1) * 32;

    uint32_t aLrow = (uint32_t)(wm + (lane & 15));
    uint32_t aLcol = (uint32_t)((lane >> 4) * 16);
    uint32_t bLrow = (uint32_t)(wn + (lane & 7) + ((lane >> 4) & 1) * 8);
    uint32_t bLcol = (uint32_t)(((lane >> 3) & 1) * 16);

    float acc[4][4][4];
#pragma unroll
    for (int mt = 0; mt < 4; mt++)
#pragma unroll
        for (int nt = 0; nt < 4; nt++)
#pragma unroll
            for (int i = 0; i < 4; i++) acc[mt][nt][i] = 0.f;

    uint4 pA[4], hB[4];
    float4 bf[8];

    // prologue: slab 0
#pragma unroll
    for (int i = 0; i < 4; i++)
        pA[i] = *(const uint4*)(arow + i * 8);
#pragma unroll
    for (int j = 0; j < 8; j++)
        bf[j] = *(const float4*)(brow + j * 4);
#pragma unroll
    for (int j = 0; j < 4; j++)
        hB[j] = make_uint4(f2h2(bf[2*j].x, bf[2*j].y), f2h2(bf[2*j].z, bf[2*j].w),
                           f2h2(bf[2*j+1].x, bf[2*j+1].y), f2h2(bf[2*j+1].z, bf[2*j+1].w));

    for (int s = 0; s < NS2; s++) {
        int buf = s & 1;
        char* At = Asm + buf * ABUF;
        char* Bt = Bsm + buf * BBUF;
#pragma unroll
        for (int i = 0; i < 4; i++) {
            *(uint4*)(At + stoff + i * 16) = pA[i];
            *(uint4*)(Bt + stoff + i * 16) = hB[i];
        }
        __syncthreads();     // single barrier per slab

        bool more = (s + 1 < NS2);
        if (more) {
            int k = (s + 1) * BKH2;
#pragma unroll
            for (int i = 0; i < 4; i++)
                pA[i] = *(const uint4*)(arow + k + i * 8);
#pragma unroll
            for (int j = 0; j < 8; j++)
                bf[j] = *(const float4*)(brow + k + j * 4);
        }

        uint32_t aTile = asB + buf * ABUF;
        uint32_t bTile = bsB + buf * BBUF;
#pragma unroll
        for (int ks = 0; ks < 4; ks++) {
            uint32_t kbA = ks * 32 + aLcol;
            uint32_t kbB = ks * 32 + bLcol;
            uint32_t a[4][4];
#pragma unroll
            for (int mt = 0; mt < 4; mt++)
                ldsm4(a[mt][0], a[mt][1], a[mt][2], a[mt][3],
                      aTile + (aLrow + mt * 16) * ROWB2 + kbA);
#pragma unroll
            for (int np = 0; np < 2; np++) {
                uint32_t b0, b1, b2, b3;
                ldsm4(b0, b1, b2, b3,
                      bTile + (bLrow + np * 16) * ROWB2 + kbB);
#pragma unroll
                for (int mt = 0; mt < 4; mt++) {
                    mma_f16(acc[mt][np * 2 + 0], a[mt], b0, b1);
                    mma_f16(acc[mt][np * 2 + 1], a[mt], b2, b3);
                }
            }
        }

        if (more) {
#pragma unroll
            for (int j = 0; j < 4; j++)
                hB[j] = make_uint4(f2h2(bf[2*j].x, bf[2*j].y), f2h2(bf[2*j].z, bf[2*j].w),
                                   f2h2(bf[2*j+1].x, bf[2*j+1].y), f2h2(bf[2*j+1].z, bf[2*j+1].w));
        }
    }

#pragma unroll
    for (int mt = 0; mt < 4; mt++) {
        int rbase = m0 + wm + mt * 16 + gid;
#pragma unroll
        for (int nt = 0; nt < 4; nt++) {
            int cbase = n0 + wn + nt * 8 + 2 * tig;
            *(float2*)&g_y[(size_t)rbase * HDIM + cbase] =
                make_float2(acc[mt][nt][0], acc[mt][nt][1]);
            *(float2*)&g_y[(size_t)(rbase + 8) * HDIM + cbase] =
                make_float2(acc[mt][nt][2], acc[mt][nt][3]);
        }
    }
}

// ---------------- combine: out[t] = y[pos0] + y[pos1] (float4) ---------------
__global__ void combine_kernel(float* __restrict__ out) {
    int i = blockIdx.x * blockDim.x + threadIdx.x;   // over T_TOK*HDIM/4
    if (i >= T_TOK * HDIM / 4) return;
    int t = i >> 8, n4 = i & 255;
    int p0 = g_token_pos[t * 2 + 0];
    int p1 = g_token_pos[t * 2 + 1];
    float4 a = *(const float4*)&g_y[(size_t)p0 * HDIM + n4 * 4];
    float4 b = *(const float4*)&g_y[(size_t)p1 * HDIM + n4 * 4];
    float4 o = make_float4(a.x + b.x, a.y + b.y, a.z + b.z, a.w + b.w);
    *(float4*)&out[(size_t)t * HDIM + n4 * 4] = o;
}

// ---------------- launcher ----------------------------------------------------
extern "C" void kernel_launch(void* const* d_in, const int* in_sizes, int n_in,
                              void* d_out, int out_size) {
    const float* x   = (const float*)d_in[0];   // (2,2048,1024)
    const float* gw  = (const float*)d_in[1];   // (8,1024)
    const float* gup = (const float*)d_in[2];   // (8,8192,1024)
    const float* dw  = (const float*)d_in[3];   // (8,1024,4096)
    float* out = (float*)d_out;                 // out (4194304) ++ logits (32768)
    float* logits = out + (size_t)T_TOK * HDIM;

    const int smem1 = 2 * 128 * ROWB1 + 2 * 2 * 128 * ROWB1;  // 61440 B
    const int smem2 = 2 * 128 * ROWB2 + 2 * 128 * ROWB2;      // 73728 B
    cudaFuncSetAttribute(gemm1_kernel, cudaFuncAttributeMaxDynamicSharedMemorySize, smem1);
    cudaFuncSetAttribute(gemm2_kernel, cudaFuncAttributeMaxDynamicSharedMemorySize, smem2);

    __half* d_x16; cudaGetSymbolAddress((void**)&d_x16, g_x16);

    cvt_kernel<<<(T_TOK * HDIM / 8 + 255) / 256, 256>>>(x, d_x16, T_TOK * HDIM / 8);
    init_kernel<<<(PADROWS + 255) / 256, 256>>>();
    router_kernel<<<T_TOK / 4, 128>>>(x, gw, logits);
    scan_kernel<<<1, 1>>>();
    scatter_kernel<<<(T_TOK + 255) / 256, 256>>>();
    gemm1_kernel<<<dim3(PADROWS / BM, FDIM / BN), 256, smem1>>>(gup);
    gemm2_kernel<<<dim3(PADROWS / BM, HDIM / BN), 256, smem2>>>(dw);
    combine_kernel<<<(T_TOK * HDIM / 4 + 255) / 256, 256>>>(out);
    (void)in_sizes; (void)n_in; (void)out_size;
}

// round 10
// speedup vs baseline: 1.3676x; 1.3676x over previous
#include <cuda_runtime.h>
#include <cuda_fp16.h>
#include <cstdint>

// Problem constants (fixed shapes)
#define T_TOK 4096
#define HDIM  1024
#define FDIM  4096
#define EDIM  8
#define BM 128
#define BN 128
#define BKH 64          // K halves per slab (4 x k16 mma steps)
#define ROWB 144        // smem row stride bytes (128 data + 16 pad)
#define PADROWS 9216    // 8192 + 8*128 worst-case segment padding
#define NS1 (HDIM / BKH)   // 16
#define NS2 (FDIM / BKH)   // 64

// ---------------- scratch (static device globals; no allocation) ----------
__device__ __align__(16) __half g_wgup[(size_t)EDIM * 2 * FDIM * HDIM];
__device__ __align__(16) __half g_wdw[(size_t)EDIM * HDIM * FDIM];
__device__ __align__(16) __half g_x16[(size_t)T_TOK * HDIM];
__device__ __align__(16) __half g_h[(size_t)PADROWS * FDIM];
__device__ __align__(16) float  g_y[(size_t)PADROWS * HDIM];
__device__ int   g_perm_token[PADROWS];
__device__ float g_perm_weight[PADROWS];
__device__ int   g_token_pos[T_TOK * 2];
__device__ int   g_te[T_TOK * 2];
__device__ float g_tw[T_TOK * 2];
__device__ int   g_counts[EDIM];
__device__ int   g_cursor[EDIM];
__device__ int   g_off[EDIM + 1];

// ---------------- helpers ---------------------------------------------------
__device__ __forceinline__ uint32_t h2u(__half2 h) { return *(uint32_t*)&h; }

__device__ __forceinline__ uint32_t smem_u32(const void* p) {
    uint32_t a;
    asm("{ .reg .u64 t; cvta.to.shared.u64 t, %1; cvt.u32.u64 %0, t; }"
        : "=r"(a) : "l"(p));
    return a;
}

__device__ __forceinline__ void ldsm4(uint32_t& r0, uint32_t& r1,
                                      uint32_t& r2, uint32_t& r3, uint32_t addr) {
    asm volatile("ldmatrix.sync.aligned.m8n8.x4.shared.b16 {%0,%1,%2,%3}, [%4];"
                 : "=r"(r0), "=r"(r1), "=r"(r2), "=r"(r3) : "r"(addr));
}

__device__ __forceinline__ void mma_f16(float c[4], const uint32_t a[4],
                                        uint32_t b0, uint32_t b1) {
    asm volatile(
        "mma.sync.aligned.m16n8k16.row.col.f32.f16.f16.f32 "
        "{%0,%1,%2,%3}, {%4,%5,%6,%7}, {%8,%9}, {%0,%1,%2,%3};\n"
        : "+f"(c[0]), "+f"(c[1]), "+f"(c[2]), "+f"(c[3])
        : "r"(a[0]), "r"(a[1]), "r"(a[2]), "r"(a[3]), "r"(b0), "r"(b1));
}

// ---------------- fp32 -> fp16 conversion (one pass per tensor) ---------------
__global__ void cvt_kernel(const float* __restrict__ s, __half* __restrict__ d,
                           int n8) {
    int i = blockIdx.x * blockDim.x + threadIdx.x;
    if (i >= n8) return;
    const float4* s4 = (const float4*)s + (size_t)i * 2;
    float4 v0 = s4[0], v1 = s4[1];
    uint4 o;
    o.x = h2u(__floats2half2_rn(v0.x, v0.y));
    o.y = h2u(__floats2half2_rn(v0.z, v0.w));
    o.z = h2u(__floats2half2_rn(v1.x, v1.y));
    o.w = h2u(__floats2half2_rn(v1.z, v1.w));
    ((uint4*)d)[i] = o;
}

// ---------------- init ------------------------------------------------------
__global__ void init_kernel() {
    int i = blockIdx.x * blockDim.x + threadIdx.x;
    if (i < PADROWS) {
        g_perm_token[i] = -1;
        g_perm_weight[i] = 0.f;
    }
    if (i < EDIM) g_counts[i] = 0;
}

// ---------------- router: logits + softmax top2 -----------------------------
__global__ void __launch_bounds__(128) router_kernel(
    const float* __restrict__ x, const float* __restrict__ gw,
    float* __restrict__ logits_out) {
    __shared__ float sgw[EDIM * HDIM];
    int tid = threadIdx.x;
    for (int i = tid; i < EDIM * HDIM; i += 128) sgw[i] = gw[i];
    __syncthreads();

    int warp = tid >> 5, lane = tid & 31;
    int t = blockIdx.x * 4 + warp;
    const float* xr = x + (size_t)t * HDIM;

    float acc[EDIM];
#pragma unroll
    for (int e = 0; e < EDIM; e++) acc[e] = 0.f;
    for (int j = lane; j < HDIM; j += 32) {
        float xv = xr[j];
#pragma unroll
        for (int e = 0; e < EDIM; e++) acc[e] = fmaf(xv, sgw[e * HDIM + j], acc[e]);
    }
#pragma unroll
    for (int e = 0; e < EDIM; e++)
#pragma unroll
        for (int o = 16; o > 0; o >>= 1)
            acc[e] += __shfl_xor_sync(0xffffffffu, acc[e], o);

    if (lane == 0) {
#pragma unroll
        for (int e = 0; e < EDIM; e++) logits_out[t * EDIM + e] = acc[e];
        int e0 = 0; float l0 = acc[0];
#pragma unroll
        for (int e = 1; e < EDIM; e++) if (acc[e] > l0) { l0 = acc[e]; e0 = e; }
        int e1 = -1; float l1 = -3.4e38f;
#pragma unroll
        for (int e = 0; e < EDIM; e++)
            if (e != e0 && acc[e] > l1) { l1 = acc[e]; e1 = e; }
        float r = expf(l1 - l0);
        float w0 = 1.f / (1.f + r);
        float w1 = r / (1.f + r);
        g_te[t * 2 + 0] = e0; g_tw[t * 2 + 0] = w0;
        g_te[t * 2 + 1] = e1; g_tw[t * 2 + 1] = w1;
        atomicAdd(&g_counts[e0], 1);
        atomicAdd(&g_counts[e1], 1);
    }
}

// ---------------- scan ------------------------------------------------------
__global__ void scan_kernel() {
    int off = 0;
    for (int e = 0; e < EDIM; e++) {
        g_off[e] = off;
        g_cursor[e] = off;
        off += ((g_counts[e] + BM - 1) / BM) * BM;
    }
    g_off[EDIM] = off;
}

// ---------------- scatter ---------------------------------------------------
__global__ void scatter_kernel() {
    int t = blockIdx.x * blockDim.x + threadIdx.x;
    if (t >= T_TOK) return;
#pragma unroll
    for (int k = 0; k < 2; k++) {
        int e = g_te[t * 2 + k];
        int pos = atomicAdd(&g_cursor[e], 1);
        g_perm_token[pos] = t;
        g_perm_weight[pos] = g_tw[t * 2 + k];
        g_token_pos[t * 2 + k] = pos;
    }
}

// ---------------- GEMM1: h = silu(x@w1^T) * (x@w3^T) * route_w ---------------
// 256 threads / 8 warps; fp16; ldmatrix; reg prefetch; ONE barrier per slab.
__global__ void __launch_bounds__(256, 1) gemm1_kernel() {
    extern __shared__ char sm1[];
    const uint32_t ABUF = 128 * ROWB;            // 18432
    const uint32_t GOFF = 128 * ROWB;            // up section inside B
    const uint32_t BBUF = 2 * 128 * ROWB;        // 36864
    char* Asm = sm1;
    char* Bsm = sm1 + 2 * ABUF;
    uint32_t asB = smem_u32(Asm);
    uint32_t bsB = smem_u32(Bsm);

    int m0 = blockIdx.x * BM;
    if (m0 >= g_off[EDIM]) return;
    int n0 = blockIdx.y * BN;
    int e = 0;
    while (m0 >= g_off[e + 1]) e++;

    int tid = threadIdx.x;
    int r = tid >> 1;             // staging row 0..127
    int seg = tid & 1;            // 64-byte half-row segment

    int tok = g_perm_token[m0 + r];
    const __half* arow = (tok >= 0)
        ? g_x16 + (size_t)tok * HDIM + seg * 32 : nullptr;
    const __half* bgrow = g_wgup + ((size_t)e * 2 * FDIM + (n0 + r)) * HDIM + seg * 32;
    const __half* burow = bgrow + (size_t)FDIM * HDIM;
    uint32_t stoff = (uint32_t)(r * ROWB + seg * 64);

    int warp = tid >> 5, lane = tid & 31;
    int gid = lane >> 2, tig = lane & 3;
    int wm = (warp & 1) * 64;
    int wn = (warp >> 1) * 32;

    uint32_t aLrow = (uint32_t)(wm + (lane & 15));
    uint32_t aLcol = (uint32_t)((lane >> 4) * 16);
    uint32_t bLrow = (uint32_t)(wn + (lane & 7) + ((lane >> 4) & 1) * 8);
    uint32_t bLcol = (uint32_t)(((lane >> 3) & 1) * 16);

    float acc[2][4][4][4];
#pragma unroll
    for (int g = 0; g < 2; g++)
#pragma unroll
        for (int mt = 0; mt < 4; mt++)
#pragma unroll
            for (int nt = 0; nt < 4; nt++)
#pragma unroll
                for (int i = 0; i < 4; i++) acc[g][mt][nt][i] = 0.f;

    const uint4 z4 = make_uint4(0, 0, 0, 0);
    uint4 pA[4], pG[4], pU[4];
#pragma unroll
    for (int i = 0; i < 4; i++) {
        pA[i] = arow ? *(const uint4*)(arow + i * 8) : z4;
        pG[i] = *(const uint4*)(bgrow + i * 8);
        pU[i] = *(const uint4*)(burow + i * 8);
    }

    for (int s = 0; s < NS1; s++) {
        int buf = s & 1;
        char* At = Asm + buf * ABUF;
        char* Bt = Bsm + buf * BBUF;
#pragma unroll
        for (int i = 0; i < 4; i++) {
            *(uint4*)(At + stoff + i * 16) = pA[i];
            *(uint4*)(Bt + stoff + i * 16) = pG[i];
            *(uint4*)(Bt + GOFF + stoff + i * 16) = pU[i];
        }
        __syncthreads();     // single barrier per slab (double-buffer safe)

        if (s + 1 < NS1) {
            int k = (s + 1) * BKH;
#pragma unroll
            for (int i = 0; i < 4; i++) {
                pA[i] = arow ? *(const uint4*)(arow + k + i * 8) : z4;
                pG[i] = *(const uint4*)(bgrow + k + i * 8);
                pU[i] = *(const uint4*)(burow + k + i * 8);
            }
        }

        uint32_t aTile = asB + buf * ABUF;
        uint32_t bTile = bsB + buf * BBUF;
#pragma unroll
        for (int ks = 0; ks < 4; ks++) {
            uint32_t kbA = ks * 32 + aLcol;
            uint32_t kbB = ks * 32 + bLcol;
            uint32_t a[4][4];
#pragma unroll
            for (int mt = 0; mt < 4; mt++)
                ldsm4(a[mt][0], a[mt][1], a[mt][2], a[mt][3],
                      aTile + (aLrow + mt * 16) * ROWB + kbA);
#pragma unroll
            for (int g = 0; g < 2; g++) {
#pragma unroll
                for (int np = 0; np < 2; np++) {
                    uint32_t b0, b1, b2, b3;
                    ldsm4(b0, b1, b2, b3,
                          bTile + g * GOFF + (bLrow + np * 16) * ROWB + kbB);
#pragma unroll
                    for (int mt = 0; mt < 4; mt++) {
                        mma_f16(acc[g][mt][np * 2 + 0], a[mt], b0, b1);
                        mma_f16(acc[g][mt][np * 2 + 1], a[mt], b2, b3);
                    }
                }
            }
        }
    }

    // epilogue: silu(gate) * up * routing_weight -> fp16 g_h
#pragma unroll
    for (int mt = 0; mt < 4; mt++) {
        int rbase = m0 + wm + mt * 16 + gid;
        float wA = g_perm_weight[rbase];
        float wB = g_perm_weight[rbase + 8];
#pragma unroll
        for (int nt = 0; nt < 4; nt++) {
            int cbase = n0 + wn + nt * 8 + 2 * tig;
            float h0 = (acc[0][mt][nt][0] / (1.f + expf(-acc[0][mt][nt][0]))) *
                       acc[1][mt][nt][0] * wA;
            float h1 = (acc[0][mt][nt][1] / (1.f + expf(-acc[0][mt][nt][1]))) *
                       acc[1][mt][nt][1] * wA;
            float h2 = (acc[0][mt][nt][2] / (1.f + expf(-acc[0][mt][nt][2]))) *
                       acc[1][mt][nt][2] * wB;
            float h3 = (acc[0][mt][nt][3] / (1.f + expf(-acc[0][mt][nt][3]))) *
                       acc[1][mt][nt][3] * wB;
            *(uint32_t*)&g_h[(size_t)rbase * FDIM + cbase] =
                h2u(__floats2half2_rn(h0, h1));
            *(uint32_t*)&g_h[(size_t)(rbase + 8) * FDIM + cbase] =
                h2u(__floats2half2_rn(h2, h3));
        }
    }
}

// ---------------- GEMM2: y = h @ w2^T ----------------------------------------
__global__ void __launch_bounds__(256, 1) gemm2_kernel() {
    extern __shared__ char sm2[];
    const uint32_t ABUF = 128 * ROWB;
    const uint32_t BBUF = 128 * ROWB;
    char* Asm = sm2;
    char* Bsm = sm2 + 2 * ABUF;
    uint32_t asB = smem_u32(Asm);
    uint32_t bsB = smem_u32(Bsm);

    int m0 = blockIdx.x * BM;
    if (m0 >= g_off[EDIM]) return;
    int n0 = blockIdx.y * BN;   // over HDIM
    int e = 0;
    while (m0 >= g_off[e + 1]) e++;

    int tid = threadIdx.x;
    int r = tid >> 1;
    int seg = tid & 1;

    const __half* arow = g_h + (size_t)(m0 + r) * FDIM + seg * 32;
    const __half* brow = g_wdw + ((size_t)e * HDIM + (n0 + r)) * FDIM + seg * 32;
    uint32_t stoff = (uint32_t)(r * ROWB + seg * 64);

    int warp = tid >> 5, lane = tid & 31;
    int gid = lane >> 2, tig = lane & 3;
    int wm = (warp & 1) * 64;
    int wn = (warp >> 1) * 32;

    uint32_t aLrow = (uint32_t)(wm + (lane & 15));
    uint32_t aLcol = (uint32_t)((lane >> 4) * 16);
    uint32_t bLrow = (uint32_t)(wn + (lane & 7) + ((lane >> 4) & 1) * 8);
    uint32_t bLcol = (uint32_t)(((lane >> 3) & 1) * 16);

    float acc[4][4][4];
#pragma unroll
    for (int mt = 0; mt < 4; mt++)
#pragma unroll
        for (int nt = 0; nt < 4; nt++)
#pragma unroll
            for (int i = 0; i < 4; i++) acc[mt][nt][i] = 0.f;

    uint4 pA[4], pB[4];
#pragma unroll
    for (int i = 0; i < 4; i++) {
        pA[i] = *(const uint4*)(arow + i * 8);
        pB[i] = *(const uint4*)(brow + i * 8);
    }

    for (int s = 0; s < NS2; s++) {
        int buf = s & 1;
        char* At = Asm + buf * ABUF;
        char* Bt = Bsm + buf * BBUF;
#pragma unroll
        for (int i = 0; i < 4; i++) {
            *(uint4*)(At + stoff + i * 16) = pA[i];
            *(uint4*)(Bt + stoff + i * 16) = pB[i];
        }
        __syncthreads();     // single barrier per slab

        if (s + 1 < NS2) {
            int k = (s + 1) * BKH;
#pragma unroll
            for (int i = 0; i < 4; i++) {
                pA[i] = *(const uint4*)(arow + k + i * 8);
                pB[i] = *(const uint4*)(brow + k + i * 8);
            }
        }

        uint32_t aTile = asB + buf * ABUF;
        uint32_t bTile = bsB + buf * BBUF;
#pragma unroll
        for (int ks = 0; ks < 4; ks++) {
            uint32_t kbA = ks * 32 + aLcol;
            uint32_t kbB = ks * 32 + bLcol;
            uint32_t a[4][4];
#pragma unroll
            for (int mt = 0; mt < 4; mt++)
                ldsm4(a[mt][0], a[mt][1], a[mt][2], a[mt][3],
                      aTile + (aLrow + mt * 16) * ROWB + kbA);
#pragma unroll
            for (int np = 0; np < 2; np++) {
                uint32_t b0, b1, b2, b3;
                ldsm4(b0, b1, b2, b3,
                      bTile + (bLrow + np * 16) * ROWB + kbB);
#pragma unroll
                for (int mt = 0; mt < 4; mt++) {
                    mma_f16(acc[mt][np * 2 + 0], a[mt], b0, b1);
                    mma_f16(acc[mt][np * 2 + 1], a[mt], b2, b3);
                }
            }
        }
    }

#pragma unroll
    for (int mt = 0; mt < 4; mt++) {
        int rbase = m0 + wm + mt * 16 + gid;
#pragma unroll
        for (int nt = 0; nt < 4; nt++) {
            int cbase = n0 + wn + nt * 8 + 2 * tig;
            *(float2*)&g_y[(size_t)rbase * HDIM + cbase] =
                make_float2(acc[mt][nt][0], acc[mt][nt][1]);
            *(float2*)&g_y[(size_t)(rbase + 8) * HDIM + cbase] =
                make_float2(acc[mt][nt][2], acc[mt][nt][3]);
        }
    }
}

// ---------------- combine: out[t] = y[pos0] + y[pos1] (float4) ---------------
__global__ void combine_kernel(float* __restrict__ out) {
    int i = blockIdx.x * blockDim.x + threadIdx.x;   // over T_TOK*HDIM/4
    if (i >= T_TOK * HDIM / 4) return;
    int t = i >> 8, n4 = i & 255;
    int p0 = g_token_pos[t * 2 + 0];
    int p1 = g_token_pos[t * 2 + 1];
    float4 a = *(const float4*)&g_y[(size_t)p0 * HDIM + n4 * 4];
    float4 b = *(const float4*)&g_y[(size_t)p1 * HDIM + n4 * 4];
    float4 o = make_float4(a.x + b.x, a.y + b.y, a.z + b.z, a.w + b.w);
    *(float4*)&out[(size_t)t * HDIM + n4 * 4] = o;
}

// ---------------- launcher ----------------------------------------------------
extern "C" void kernel_launch(void* const* d_in, const int* in_sizes, int n_in,
                              void* d_out, int out_size) {
    const float* x   = (const float*)d_in[0];   // (2,2048,1024)
    const float* gw  = (const float*)d_in[1];   // (8,1024)
    const float* gup = (const float*)d_in[2];   // (8,8192,1024)
    const float* dw  = (const float*)d_in[3];   // (8,1024,4096)
    float* out = (float*)d_out;                 // out (4194304) ++ logits (32768)
    float* logits = out + (size_t)T_TOK * HDIM;

    const int smem1 = 2 * 128 * ROWB + 2 * 2 * 128 * ROWB;  // 110592 B
    const int smem2 = 2 * 128 * ROWB + 2 * 128 * ROWB;      //  73728 B
    cudaFuncSetAttribute(gemm1_kernel, cudaFuncAttributeMaxDynamicSharedMemorySize, smem1);
    cudaFuncSetAttribute(gemm2_kernel, cudaFuncAttributeMaxDynamicSharedMemorySize, smem2);

    __half* d_wgup; cudaGetSymbolAddress((void**)&d_wgup, g_wgup);
    __half* d_wdw;  cudaGetSymbolAddress((void**)&d_wdw,  g_wdw);
    __half* d_x16;  cudaGetSymbolAddress((void**)&d_x16,  g_x16);

    // one-time host-side stream/event setup (no device memory involved)
    static cudaStream_t s2 = nullptr, s3 = nullptr;
    static cudaEvent_t evFork = nullptr, evDW = nullptr, evRoute = nullptr;
    if (!s2) {
        cudaStreamCreateWithFlags(&s2, cudaStreamNonBlocking);
        cudaStreamCreateWithFlags(&s3, cudaStreamNonBlocking);
        cudaEventCreateWithFlags(&evFork, cudaEventDisableTiming);
        cudaEventCreateWithFlags(&evDW, cudaEventDisableTiming);
        cudaEventCreateWithFlags(&evRoute, cudaEventDisableTiming);
    }

    // fork point
    cudaEventRecord(evFork, 0);
    cudaStreamWaitEvent(s2, evFork, 0);
    cudaStreamWaitEvent(s3, evFork, 0);

    // s2: down-weight conversion (overlaps cvt_gup + gemm1 on main stream)
    cvt_kernel<<<(EDIM * HDIM * FDIM / 8 + 255) / 256, 256, 0, s2>>>(
        dw, d_wdw, EDIM * HDIM * FDIM / 8);
    cudaEventRecord(evDW, s2);

    // s3: routing chain (overlaps cvt_gup on main stream)
    init_kernel<<<(PADROWS + 255) / 256, 256, 0, s3>>>();
    router_kernel<<<T_TOK / 4, 128, 0, s3>>>(x, gw, logits);
    scan_kernel<<<1, 1, 0, s3>>>();
    scatter_kernel<<<(T_TOK + 255) / 256, 256, 0, s3>>>();
    cudaEventRecord(evRoute, s3);

    // main stream: x + gate_up conversion, then GEMMs
    cvt_kernel<<<(T_TOK * HDIM / 8 + 255) / 256, 256>>>(x, d_x16,
        T_TOK * HDIM / 8);
    cvt_kernel<<<(EDIM * 2 * FDIM * HDIM / 8 + 255) / 256, 256>>>(gup, d_wgup,
        EDIM * 2 * FDIM * HDIM / 8);

    cudaStreamWaitEvent(0, evRoute, 0);   // scatter results ready
    gemm1_kernel<<<dim3(PADROWS / BM, FDIM / BN), 256, smem1>>>();

    cudaStreamWaitEvent(0, evDW, 0);      // fp16 down weights ready
    gemm2_kernel<<<dim3(PADROWS / BM, HDIM / BN), 256, smem2>>>();
    combine_kernel<<<(T_TOK * HDIM / 4 + 255) / 256, 256>>>(out);
    (void)in_sizes; (void)n_in; (void)out_size;
}